// round 8
// baseline (speedup 1.0000x reference)
#include <cuda_runtime.h>
#include <cuda_bf16.h>
#include <cstdint>

// Chamfer loss, B=4, N=M=8192, D=3.
//   dist(i,j) = ||a_i||^2 + ( ||b_j||^2 - 2 a_i . b_j )
// 2 launches: init (min slots + ticket), chamfer (per-block B-slice pack in
// smem + fma-bound min loop + atomicMin merge + last-block final reduction).
// Hot loop per B-group per warp: 4x LDS.128 + 24 FFMA2 (RF-bank rt~3 => binder)
// + 16 FMNMX (alu, hidden). Mins merged via atomicMin on nonneg-float-as-uint
// (order-independent => deterministic); final sum in fixed index order.

#define BATCH   4
#define NPTS    8192
#define SB      16               // B slices
#define SLICE_P 512              // B points per slice
#define SLICE_G (SLICE_P / 4)    // 128 quad-groups, 8KB packed smem
#define BLK     128
#define APT     4                // A points per thread
#define ACHUNK  (BLK * APT)      // 512
#define NCHUNK  (NPTS / ACHUNK)  // 16
#define NMINS   (2 * BATCH * NPTS)   // 65536
#define TOTBLKS (NCHUNK * BATCH * 2 * SB)  // 2048

__device__ unsigned g_minbits[NMINS];
__device__ unsigned g_ticket;

#define FMA_F32X2(d, a, b, c) \
    asm("fma.rn.f32x2 %0, %1, %2, %3;" : "=l"(d) : "l"(a), "l"(b), "l"(c))
#define PACK2_SAME(out, r) \
    asm("mov.b64 %0, {%1, %1};" : "=l"(out) : "r"(r))
#define UNPACK_F32X2(lo, hi, in) \
    asm("mov.b64 {%0, %1}, %2;" : "=r"(lo), "=r"(hi) : "l"(in))

__global__ __launch_bounds__(256) void init_kernel()
{
    if (blockIdx.x == 0 && threadIdx.x == 0) g_ticket = 0;
    int idx = blockIdx.x * 256 + threadIdx.x;        // 16384 uint4 slots
    ((uint4*)g_minbits)[idx] = make_uint4(0x7F800000u, 0x7F800000u,
                                          0x7F800000u, 0x7F800000u);
}

__global__ __launch_bounds__(BLK) void chamfer_kernel(
    const float* __restrict__ x, const float* __restrict__ y,
    float* __restrict__ out)
{
    __shared__ float4 sy[SLICE_G * 4];               // 8 KB packed B slice
    __shared__ float  sred[BLK];
    __shared__ bool   islast;

    int dir   = blockIdx.z >> 4;                     // 0: x->y, 1: y->x
    int slice = blockIdx.z & (SB - 1);
    int b     = blockIdx.y;
    int chunk = blockIdx.x;

    const float* __restrict__ A    = dir ? y : x;
    const float* __restrict__ Braw = dir ? x : y;

    // ---- pack this block's B slice (512 pts) straight into smem ----
    // thread t packs quad-group t: points 4t..4t+3 (12 floats = 3 float4)
    {
        const float4* bsrc = (const float4*)(Braw +
            ((size_t)b * NPTS + slice * SLICE_P) * 3);
        float4 r0 = bsrc[threadIdx.x * 3 + 0];
        float4 r1 = bsrc[threadIdx.x * 3 + 1];
        float4 r2 = bsrc[threadIdx.x * 3 + 2];
        // coord0 of pts 0..3, coord1, coord2, norms
        sy[threadIdx.x * 4 + 0] =
            make_float4(-2.0f*r0.x, -2.0f*r0.w, -2.0f*r1.z, -2.0f*r2.y);
        sy[threadIdx.x * 4 + 1] =
            make_float4(-2.0f*r0.y, -2.0f*r1.x, -2.0f*r1.w, -2.0f*r2.z);
        sy[threadIdx.x * 4 + 2] =
            make_float4(-2.0f*r0.z, -2.0f*r1.y, -2.0f*r2.x, -2.0f*r2.w);
        sy[threadIdx.x * 4 + 3] = make_float4(
            r0.x*r0.x + r0.y*r0.y + r0.z*r0.z,
            r0.w*r0.w + r1.x*r1.x + r1.y*r1.y,
            r1.z*r1.z + r1.w*r1.w + r2.x*r2.x,
            r2.y*r2.y + r2.z*r2.z + r2.w*r2.w);
    }

    // ---- load 4 consecutive A points (48B, 16B-aligned) ----
    int i0 = chunk * ACHUNK + threadIdx.x * APT;
    const float4* ap = (const float4*)(A + ((size_t)b * NPTS + i0) * 3);
    float4 q0 = ap[0], q1 = ap[1], q2 = ap[2];

    float a0c[APT] = {q0.x, q0.w, q1.z, q2.y};
    float a1c[APT] = {q0.y, q1.x, q1.w, q2.z};
    float a2c[APT] = {q0.z, q1.y, q2.x, q2.w};

    unsigned long long ax[APT], ay[APT], az[APT];
    float a2n[APT];
    #pragma unroll
    for (int j = 0; j < APT; ++j) {
        PACK2_SAME(ax[j], __float_as_uint(a0c[j]));
        PACK2_SAME(ay[j], __float_as_uint(a1c[j]));
        PACK2_SAME(az[j], __float_as_uint(a2c[j]));
        a2n[j] = a0c[j]*a0c[j] + a1c[j]*a1c[j] + a2c[j]*a2c[j];
    }

    float m[APT][4];
    #pragma unroll
    for (int j = 0; j < APT; ++j)
        m[j][0] = m[j][1] = m[j][2] = m[j][3] = 1e30f;

    __syncthreads();

    // ---- main loop: 128 groups x (4 LDS.128 + 24 FFMA2 + 16 FMNMX) ----
    const ulonglong2* sp = (const ulonglong2*)sy;
    #pragma unroll 2
    for (int g = 0; g < SLICE_G; ++g) {
        ulonglong2 p0 = sp[g * 4 + 0];   // {-2b0 ab, -2b0 cd}
        ulonglong2 p1 = sp[g * 4 + 1];   // {-2b1 ab, -2b1 cd}
        ulonglong2 p2 = sp[g * 4 + 2];   // {-2b2 ab, -2b2 cd}
        ulonglong2 p3 = sp[g * 4 + 3];   // {n   ab,  n   cd}

        #pragma unroll
        for (int j = 0; j < APT; ++j) {
            unsigned long long tab, tcd;
            FMA_F32X2(tab, ax[j], p0.x, p3.x);
            FMA_F32X2(tcd, ax[j], p0.y, p3.y);
            FMA_F32X2(tab, ay[j], p1.x, tab);
            FMA_F32X2(tcd, ay[j], p1.y, tcd);
            FMA_F32X2(tab, az[j], p2.x, tab);
            FMA_F32X2(tcd, az[j], p2.y, tcd);

            unsigned lo, hi;
            UNPACK_F32X2(lo, hi, tab);
            m[j][0] = fminf(m[j][0], __uint_as_float(lo));
            m[j][1] = fminf(m[j][1], __uint_as_float(hi));
            UNPACK_F32X2(lo, hi, tcd);
            m[j][2] = fminf(m[j][2], __uint_as_float(lo));
            m[j][3] = fminf(m[j][3], __uint_as_float(hi));
        }
    }

    // ---- fold, add ||a||^2, clamp >=0, merge slices via atomicMin ----
    unsigned base = (unsigned)((dir * BATCH + b) * NPTS + i0);
    #pragma unroll
    for (int j = 0; j < APT; ++j) {
        float mm  = fminf(fminf(m[j][0], m[j][1]), fminf(m[j][2], m[j][3]));
        float val = fmaxf(a2n[j] + mm, 0.0f);
        atomicMin(&g_minbits[base + j], __float_as_uint(val));
    }

    // ---- last-block final reduction (threadFenceReduction pattern) ----
    __threadfence();
    __syncthreads();
    if (threadIdx.x == 0) {
        unsigned t = atomicAdd(&g_ticket, 1u);
        islast = (t == TOTBLKS - 1);
    }
    __syncthreads();

    if (islast) {
        __threadfence();                 // acquire: see all blocks' mins
        const uint4* src = (const uint4*)g_minbits;
        float sum = 0.0f;
        // 16384 uint4 / 128 threads = 128 each, fixed per-thread order
        for (int k = 0; k < NMINS / 4 / BLK; ++k) {
            uint4 v = src[threadIdx.x + k * BLK];
            sum += __uint_as_float(v.x) + __uint_as_float(v.y)
                 + __uint_as_float(v.z) + __uint_as_float(v.w);
        }
        sred[threadIdx.x] = sum;
        __syncthreads();
        #pragma unroll
        for (int st = BLK / 2; st > 0; st >>= 1) {
            if (threadIdx.x < st) sred[threadIdx.x] += sred[threadIdx.x + st];
            __syncthreads();
        }
        if (threadIdx.x == 0)
            out[0] = sred[0] * (1.0f / (float)(BATCH * NPTS));
    }
}

extern "C" void kernel_launch(void* const* d_in, const int* in_sizes, int n_in,
                              void* d_out, int out_size)
{
    (void)in_sizes; (void)n_in; (void)out_size;
    const float* x = (const float*)d_in[0];
    const float* y = (const float*)d_in[1];
    float* out = (float*)d_out;

    init_kernel<<<64, 256>>>();

    dim3 grid(NCHUNK, BATCH, 2 * SB);               // 16 x 4 x 32 = 2048 blocks
    chamfer_kernel<<<grid, BLK>>>(x, y, out);
}